// round 9
// baseline (speedup 1.0000x reference)
#include <cuda_runtime.h>
#include <cstddef>

// SpanRepresentation: out[b, s, :] = concat(x[b,start,:], x[b,end,:], wemb[wid,:])
// B=16, L=512, D=768, W=8, WD=64, NS=4068. Spans ordered by width 1..8, then start.
//
// R9: smem-staged gather with per-thread streaming stores.
//  - CTA = (b, tile of 8 starts). Stages 15 x rows (46 KB) + wemb into SMEM once.
//  - Warp w handles width w+1: writes 8 output rows that form one CONTIGUOUS
//    51 KB region of the output (off(w)+s0 .. +s0+7), streaming each 6400 B row
//    left-to-right in 512 B warp chunks -> best DRAM write page locality
//    (the property that gave R3 its 75.9% DRAM) while x is DRAM-read ~once
//    (the property that gave R8 its low L2/L1 pressure).
//  - Full per-thread STG issue concurrency (R7's TMA variant lost this).

constexpr int B    = 16;
constexpr int L    = 512;
constexpr int D    = 768;
constexpr int WD   = 64;
constexpr int NS   = 4068;

constexpr int T       = 8;              // starts per tile
constexpr int TILES   = L / T;          // 64
constexpr int MAXROWS = T + 7;          // 15
constexpr int D4      = D / 4;          // 192 float4 per x row
constexpr int WD4     = WD / 4;         // 16
constexpr int ROW4    = (2 * D + WD) / 4;  // 400 float4 per output row

__global__ __launch_bounds__(256, 4)
void span_tile_stg_kernel(const float4* __restrict__ x,      // [B, L, D/4]
                          const float4* __restrict__ wemb,   // [8, WD/4]
                          float4* __restrict__ out)          // [B*NS, ROW4]
{
    __shared__ float4 sx[MAXROWS * D4];   // 46080 B
    __shared__ float4 sw[8 * WD4];        //  2048 B  (48128 total, occ 4)

    const int b   = blockIdx.y;
    const int s0  = blockIdx.x * T;
    const int tid = threadIdx.x;

    // ---- stage x rows [s0, s0+nrows) and wemb (coalesced LDG.128) ----
    const int nrows = min(MAXROWS, L - s0);
    const float4* xsrc = x + ((size_t)b * L + s0) * D4;
    const int nf4 = nrows * D4;
    #pragma unroll 4
    for (int i = tid; i < nf4; i += 256) sx[i] = __ldg(&xsrc[i]);
    if (tid < 8 * WD4) sw[tid] = __ldg(&wemb[tid]);
    __syncthreads();

    // ---- warp w = width w+1; each warp streams a contiguous output region ----
    const int w    = tid >> 5;        // 0..7
    const int lane = tid & 31;
    const int off  = 512 * w - (w * (w - 1)) / 2;   // cumulative span offset
    const size_t base = (size_t)b * NS;

    #pragma unroll
    for (int j = 0; j < T; ++j) {
        const int start = s0 + j;
        if (start + w > L - 1) break;            // span must fit (only last tile)
        float4* __restrict__ o = out + (base + off + start) * ROW4;
        const float4* __restrict__ rs = sx + j * D4;          // h_start row
        const float4* __restrict__ re = sx + (j + w) * D4;    // h_end row

        #pragma unroll
        for (int i = lane; i < D4; i += 32)      // 6 iters: h_start segment
            __stcs(&o[i], rs[i]);
        #pragma unroll
        for (int i = lane; i < D4; i += 32)      // 6 iters: h_end segment
            __stcs(&o[D4 + i], re[i]);
        if (lane < WD4)                          // width-embedding segment
            __stcs(&o[2 * D4 + lane], sw[w * WD4 + lane]);
    }
}

extern "C" void kernel_launch(void* const* d_in, const int* in_sizes, int n_in,
                              void* d_out, int out_size)
{
    const float4* x    = (const float4*)d_in[0];   // [16, 512, 768] fp32
    const float4* wemb = (const float4*)d_in[1];   // [8, 64] fp32
    float4* out        = (float4*)d_out;           // [16, 4068, 1600] fp32

    (void)in_sizes; (void)n_in; (void)out_size;

    dim3 grid(TILES, B);   // 64 x 16 = 1024 CTAs
    dim3 block(256);       // 8 warps: one per width
    span_tile_stg_kernel<<<grid, block>>>(x, wemb, out);
}

// round 13
// speedup vs baseline: 1.0897x; 1.0897x over previous
#include <cuda_runtime.h>
#include <cstddef>

// SpanRepresentation: out[b, s, :] = concat(x[b,start,:], x[b,end,:], wemb[wid,:])
// B=16, L=512, D=768, W=8, WD=64, NS=4068. Spans ordered by width 1..8, then start.
//
// R12 = R10 resubmission (R11 was an infra failure; kernel never ran).
// R3 shape (one CTA per output row, 128 threads, full-chip store concurrency)
// with the row loop hand-unrolled into 4 phases per thread, ALL loads issued
// before any store (per-thread MLP 4), warp-aligned segment boundaries:
//   phase0: j = tid        in [  0,128)  -> h_start
//   phase1: j = tid+128    in [128,256)  -> h_start (tid<64) | h_end (tid>=64)
//   phase2: j = tid+256    in [256,384)  -> h_end
//   phase3: j = tid+384    in [384,400)  -> wemb (lanes 0..15 of warp 0 only)

constexpr int B    = 16;
constexpr int L    = 512;
constexpr int D    = 768;
constexpr int WD   = 64;
constexpr int NS   = 4068;

constexpr int D4   = D / 4;              // 192
constexpr int WD4  = WD / 4;             // 16
constexpr int ROW4 = (2 * D + WD) / 4;   // 400

__global__ __launch_bounds__(128, 16)
void span_repr_kernel(const float4* __restrict__ x,      // [B, L, D/4]
                      const float4* __restrict__ wemb,   // [8, WD/4]
                      float4* __restrict__ out)          // [B*NS, ROW4]
{
    const int row = blockIdx.x;
    const int b   = row / NS;
    const int s   = row - b * NS;
    const int tid = threadIdx.x;

    // width bucket (block-uniform, 7 compares)
    int wid = 0;
    wid += (s >= 512);
    wid += (s >= 1023);
    wid += (s >= 1533);
    wid += (s >= 2042);
    wid += (s >= 2550);
    wid += (s >= 3057);
    wid += (s >= 3563);
    const int off   = 512 * wid - (wid * (wid - 1)) / 2;  // cumulative span offset
    const int start = s - off;
    const int end   = start + wid;

    const float4* __restrict__ xs = x    + ((size_t)b * L + start) * D4;
    const float4* __restrict__ xe = x    + ((size_t)b * L + end)   * D4;
    const float4* __restrict__ wf = wemb + (size_t)wid * WD4;
    float4* __restrict__ o        = out  + (size_t)row * ROW4;

    // ---- issue all loads first (MLP 4) ----
    const float4 v0 = __ldg(&xs[tid]);                                   // j = tid
    const float4 v1 = (tid < 64) ? __ldg(&xs[tid + 128])                 // j = tid+128
                                 : __ldg(&xe[tid + 128 - D4]);
    const float4 v2 = __ldg(&xe[tid + 256 - D4]);                        // j = tid+256
    float4 v3;
    if (tid < WD4) v3 = __ldg(&wf[tid]);                                 // j = tid+384

    // ---- store burst (streaming: output is touched once; keep x in L2) ----
    __stcs(&o[tid],        v0);
    __stcs(&o[tid + 128],  v1);
    __stcs(&o[tid + 256],  v2);
    if (tid < WD4) __stcs(&o[tid + 384], v3);
}

extern "C" void kernel_launch(void* const* d_in, const int* in_sizes, int n_in,
                              void* d_out, int out_size)
{
    const float4* x    = (const float4*)d_in[0];   // [16, 512, 768] fp32
    const float4* wemb = (const float4*)d_in[1];   // [8, 64] fp32
    float4* out        = (float4*)d_out;           // [16, 4068, 1600] fp32

    (void)in_sizes; (void)n_in; (void)out_size;

    dim3 grid(B * NS);   // 65088 CTAs, one output row each
    dim3 block(128);
    span_repr_kernel<<<grid, block>>>(x, wemb, out);
}